// round 10
// baseline (speedup 1.0000x reference)
#include <cuda_runtime.h>
#include <cstdint>
#include <cstddef>
#include <math.h>

#define Bn 4
#define Sn 2048
#define Dn 1024
#define Hn 16
#define DKn 64

// ---------------------------------------------------------------------------
// Scratch (alloc-free rule: __device__ globals)
// ---------------------------------------------------------------------------
__device__ float g_qkv[(size_t)3 * Bn * Hn * Sn * DKn];   // [q][b][h][s][k], tf32-valued
__device__ float g_attn[(size_t)Bn * Sn * Dn];            // [b][s][h*64+d], tf32-valued
__device__ float g_xt[(size_t)Bn * Sn * Dn];              // rna(x)
__device__ float g_wt[(size_t)3 * Hn * DKn * Dn];         // rna(w_qkv)
__device__ float g_wot[(size_t)Dn * Dn];                  // rna(w_o)

// ---------------------------------------------------------------------------
// PTX helpers (sm_100 baseline)
// ---------------------------------------------------------------------------
__device__ __forceinline__ uint32_t smem_u32(const void* p) {
    uint32_t a;
    asm("{ .reg .u64 t; cvta.to.shared.u64 t, %1; cvt.u32.u64 %0, t; }"
        : "=r"(a) : "l"(p));
    return a;
}

__device__ __forceinline__ void cp16(uint32_t dst, const void* src) {
    asm volatile("cp.async.cg.shared.global [%0], [%1], 16;"
                 :: "r"(dst), "l"(src));
}
#define CP_COMMIT() asm volatile("cp.async.commit_group;" ::: "memory")
#define CP_WAIT(n)  asm volatile("cp.async.wait_group %0;" :: "n"(n) : "memory")

__device__ __forceinline__ float tf32r(float x) {
    uint32_t u;
    asm("cvt.rna.tf32.f32 %0, %1;" : "=r"(u) : "f"(x));
    return __uint_as_float(u);
}

// ldmatrix on fp32 data viewed as b16 pairs: lane L receives row L/4,
// float-column L%4 of each 8x8-float matrix -> exact tf32 fragment layout.
__device__ __forceinline__ void ldsm4(uint32_t* r, uint32_t addr) {
    asm volatile("ldmatrix.sync.aligned.m8n8.x4.shared.b16 {%0,%1,%2,%3}, [%4];"
                 : "=r"(r[0]), "=r"(r[1]), "=r"(r[2]), "=r"(r[3]) : "r"(addr));
}

__device__ __forceinline__ void mma_tf32(float* d, const uint32_t* a, const uint32_t* b) {
    asm volatile("mma.sync.aligned.m16n8k8.row.col.f32.tf32.tf32.f32 "
                 "{%0,%1,%2,%3}, {%4,%5,%6,%7}, {%8,%9}, {%0,%1,%2,%3};"
                 : "+f"(d[0]), "+f"(d[1]), "+f"(d[2]), "+f"(d[3])
                 : "r"(a[0]), "r"(a[1]), "r"(a[2]), "r"(a[3]), "r"(b[0]), "r"(b[1]));
}

// ---------------------------------------------------------------------------
// Elementwise rna(tf32) pre-pass
// ---------------------------------------------------------------------------
__global__ void __launch_bounds__(256) cvt_kernel(
    const float4* __restrict__ in, float4* __restrict__ outp, int n4)
{
    int i = blockIdx.x * 256 + threadIdx.x;
    if (i >= n4) return;
    float4 v = in[i];
    v.x = tf32r(v.x); v.y = tf32r(v.y); v.z = tf32r(v.z); v.w = tf32r(v.w);
    outp[i] = v;
}

// ---------------------------------------------------------------------------
// tf32 GEMM: C[M,N] = A[M,K] * B[N,K]^T, fp32 accumulate.
// 128x128 CTA tile, BK=32, 4 warps (2x2), warp tile 64x64 (32 mma : 8 ldsm
// per k8), 3-stage cp.async, single barrier per K-chunk.
// ---------------------------------------------------------------------------
#define GLDS  36
#define GMATF (128 * GLDS)
#define GSTG  (2 * GMATF * 4)
#define G_SMEM (3 * GSTG)

template <int REMAP>
__global__ void __launch_bounds__(128, 2) gemm_tf32(
    const float* __restrict__ A, const float* __restrict__ Bm,
    float* __restrict__ C, int M, int N, int K)
{
    extern __shared__ float sg[];
    const uint32_t sb = smem_u32(sg);
    const int tid = threadIdx.x, lane = tid & 31, wid = tid >> 5;
    const int wm = wid >> 1, wn = wid & 1;              // 2 x 2 warp grid
    const int lr = lane >> 2, lc = lane & 3;
    const int bm = blockIdx.y * 128, bn = blockIdx.x * 128;
    const int NC = K >> 5;

    const char* gA = (const char*)(A + (size_t)bm * K);
    const char* gB = (const char*)(Bm + (size_t)bn * K);

    auto fill = [&](int s, int c) {
        const uint32_t base = sb + s * GSTG;
        const int kof = c * 32;
#pragma unroll
        for (int u = 0; u < 8; u++) {
            const int ch = tid + u * 128;               // 0..1023
            const int row = ch >> 3, col = (ch & 7) << 2;
            cp16(base + (uint32_t)(row * GLDS + col) * 4,
                 gA + ((size_t)row * K + kof + col) * 4);
            cp16(base + (uint32_t)GMATF * 4 + (uint32_t)(row * GLDS + col) * 4,
                 gB + ((size_t)row * K + kof + col) * 4);
        }
        CP_COMMIT();
    };

    fill(0, 0);
    if (NC > 1) fill(1, 1);

    float acc[4][8][4];
#pragma unroll
    for (int i = 0; i < 4; i++)
#pragma unroll
        for (int j = 0; j < 8; j++)
#pragma unroll
            for (int e = 0; e < 4; e++) acc[i][j][e] = 0.f;

    // ldmatrix lane addressing (float-element offsets)
    const uint32_t aOff = (uint32_t)((wm * 64 + (lane & 15)) * GLDS + ((lane >> 4) << 2)) * 4;
    const uint32_t bOff = (uint32_t)((wn * 64 + (((lane >> 4) & 1) << 3) + (lane & 7)) * GLDS
                                     + (((lane >> 3) & 1) << 2)) * 4;

    for (int c = 0; c < NC; c++) {
        const int s = c % 3;
        if (c < NC - 1) { CP_WAIT(1); } else { CP_WAIT(0); }
        __syncthreads();
        // Barrier above certifies all warps finished reading stage (c+2)%3
        // (read at iter c-1) -> safe to refill it now, overlapping compute.
        if (c + 2 < NC) fill((c + 2) % 3, c + 2);

        const uint32_t aB = sb + s * GSTG + aOff;
        const uint32_t bB = sb + s * GSTG + (uint32_t)GMATF * 4 + bOff;

#pragma unroll
        for (int k0 = 0; k0 < 32; k0 += 8) {
            uint32_t a[4][4], bq[4][4];
#pragma unroll
            for (int i = 0; i < 4; i++)
                ldsm4(a[i], aB + (uint32_t)(i * 16 * GLDS + k0) * 4);
#pragma unroll
            for (int jp = 0; jp < 4; jp++)
                ldsm4(bq[jp], bB + (uint32_t)(jp * 16 * GLDS + k0) * 4);
#pragma unroll
            for (int jp = 0; jp < 4; jp++)
#pragma unroll
                for (int i = 0; i < 4; i++) {
                    mma_tf32(acc[i][2 * jp],     a[i], &bq[jp][0]);
                    mma_tf32(acc[i][2 * jp + 1], a[i], &bq[jp][2]);
                }
        }
        // no trailing barrier: next iteration's top barrier provides it
    }

    const int fc = lc << 1;
#pragma unroll
    for (int i = 0; i < 4; i++) {
#pragma unroll
        for (int j = 0; j < 8; j++) {
            const int n = bn + wn * 64 + j * 8 + fc;
#pragma unroll
            for (int half = 0; half < 2; half++) {
                const int m = bm + wm * 64 + i * 16 + lr + half * 8;
                float2 v = make_float2(acc[i][j][half * 2], acc[i][j][half * 2 + 1]);
                if (REMAP == 0) {
                    v.x = tf32r(v.x); v.y = tf32r(v.y);
                    const int q = n >> 10, h = (n >> 6) & 15, kd = n & 63;
                    const int b = m >> 11, s2 = m & 2047;
                    *(float2*)&g_qkv[((((size_t)q * Bn + b) * Hn + h) * Sn + s2) * DKn + kd] = v;
                } else {
                    *(float2*)&C[(size_t)m * N + n] = v;
                }
            }
        }
    }
}

// ---------------------------------------------------------------------------
// Causal flash attention on tf32 mma.sync.  (unchanged from R9)
// ---------------------------------------------------------------------------
#define FQL 68                          // Q/K stride (bank = 4*lr+lc)
#define FVL 72                          // V stride  (bank = 8*lc+lr)
#define FKBYTES (64 * FQL * 4)          // 17408
#define FVBYTES (64 * FVL * 4)          // 18432
#define FSTG (FKBYTES + FVBYTES)        // 35840
#define F_SMEM (128 * FQL * 4 + 2 * FSTG)  // 106496

__global__ void __launch_bounds__(256, 2) flash_tf32()
{
    extern __shared__ float smf[];
    float* Qs = smf;                          // [128][FQL], pre-scaled by 1/8
    const uint32_t sbQ  = smem_u32(smf);
    const uint32_t sbKV = sbQ + 128 * FQL * 4;

    const int qt = (Sn / 128 - 1) - blockIdx.x;   // largest workload first
    const int h = blockIdx.y, b = blockIdx.z;
    const int tid = threadIdx.x;
    const int lane = tid & 31, wid = tid >> 5;
    const int lr = lane >> 2, lc = lane & 3;

    const size_t headoff = (((size_t)b * Hn + h) * Sn) * DKn;
    const size_t plane = (size_t)Bn * Hn * Sn * DKn;
    const float* Qg = g_qkv + headoff;
    const float* Kg = g_qkv + plane + headoff;
    const float* Vg = g_qkv + 2 * plane + headoff;

    auto fillKV = [&](int s, int kt) {
        const uint32_t base = sbKV + s * FSTG;
#pragma unroll
        for (int u = 0; u < 4; u++) {
            const int ch = tid + u * 256;
            const int r = ch >> 4, c = (ch & 15) << 2;
            const float* src = Kg + (size_t)(kt * 64 + r) * DKn + c;
            cp16(base + (uint32_t)(r * FQL + c) * 4, src);
            cp16(base + FKBYTES + (uint32_t)(r * FVL + c) * 4, src + plane);
        }
        CP_COMMIT();
    };

    const int KT = 2 * qt + 2;
    fillKV(0, 0);

#pragma unroll
    for (int u = 0; u < 8; u++) {
        const int idx = tid + u * 256;
        const int r = idx >> 4, c = (idx & 15) << 2;
        float4 q = *(const float4*)(Qg + (size_t)(qt * 128 + r) * DKn + c);
        q.x *= 0.125f; q.y *= 0.125f; q.z *= 0.125f; q.w *= 0.125f;
        *(float4*)(Qs + r * FQL + c) = q;
    }

    float oacc[8][4];
#pragma unroll
    for (int j = 0; j < 8; j++)
#pragma unroll
        for (int e = 0; e < 4; e++) oacc[j][e] = 0.f;
    float m0 = -1e30f, m1 = -1e30f, l0 = 0.f, l1 = 0.f;

    // ldmatrix lane addressing
    const uint32_t qOff = sbQ +
        (uint32_t)((wid * 16 + (lane & 15)) * FQL + ((lane >> 4) << 2)) * 4;
    const uint32_t kOff =
        (uint32_t)(((((lane >> 4) & 1) << 3) + (lane & 7)) * FQL + (((lane >> 3) & 1) << 2)) * 4;

    for (int kt = 0; kt < KT; kt++) {
        const int s = kt & 1;
        CP_WAIT(0);
        __syncthreads();
        // Barrier certifies all warps finished reading stage s^1 at kt-1
        // (and makes the Q-tile stores visible on kt==0) -> refill s^1 now.
        if (kt + 1 < KT) fillKV(s ^ 1, kt + 1);

        const uint32_t ksb = sbKV + s * FSTG;
        const float* Vs = smf + (ksb - sbQ + FKBYTES) / 4;

        // S = Q K^T
        float sacc[8][4];
#pragma unroll
        for (int j = 0; j < 8; j++)
#pragma unroll
            for (int e = 0; e < 4; e++) sacc[j][e] = 0.f;

#pragma unroll
        for (int k0 = 0; k0 < 64; k0 += 8) {
            uint32_t a[4];
            ldsm4(a, qOff + (uint32_t)k0 * 4);
#pragma unroll
            for (int jp = 0; jp < 4; jp++) {
                uint32_t kq[4];
                ldsm4(kq, ksb + kOff + (uint32_t)(jp * 16 * FQL + k0) * 4);
                mma_tf32(sacc[2 * jp],     a, &kq[0]);
                mma_tf32(sacc[2 * jp + 1], a, &kq[2]);
            }
        }

        // Causal mask (only tiles touching the diagonal)
        if (kt * 64 + 63 > qt * 128) {
            const int qr0 = qt * 128 + wid * 16 + lr;
#pragma unroll
            for (int j = 0; j < 8; j++) {
                const int kc = kt * 64 + j * 8 + 2 * lc;
                if (kc     > qr0)     sacc[j][0] = -1e30f;
                if (kc + 1 > qr0)     sacc[j][1] = -1e30f;
                if (kc     > qr0 + 8) sacc[j][2] = -1e30f;
                if (kc + 1 > qr0 + 8) sacc[j][3] = -1e30f;
            }
        }

        // Warp-local online softmax
        float pm0 = -1e30f, pm1 = -1e30f;
#pragma unroll
        for (int j = 0; j < 8; j++) {
            pm0 = fmaxf(pm0, fmaxf(sacc[j][0], sacc[j][1]));
            pm1 = fmaxf(pm1, fmaxf(sacc[j][2], sacc[j][3]));
        }
        pm0 = fmaxf(pm0, __shfl_xor_sync(0xffffffffu, pm0, 1));
        pm0 = fmaxf(pm0, __shfl_xor_sync(0xffffffffu, pm0, 2));
        pm1 = fmaxf(pm1, __shfl_xor_sync(0xffffffffu, pm1, 1));
        pm1 = fmaxf(pm1, __shfl_xor_sync(0xffffffffu, pm1, 2));
        const float nm0 = fmaxf(m0, pm0), nm1 = fmaxf(m1, pm1);

        float sum0 = 0.f, sum1 = 0.f;
#pragma unroll
        for (int j = 0; j < 8; j++) {
            sacc[j][0] = __expf(sacc[j][0] - nm0);
            sacc[j][1] = __expf(sacc[j][1] - nm0);
            sacc[j][2] = __expf(sacc[j][2] - nm1);
            sacc[j][3] = __expf(sacc[j][3] - nm1);
            sum0 += sacc[j][0] + sacc[j][1];
            sum1 += sacc[j][2] + sacc[j][3];
        }
        sum0 += __shfl_xor_sync(0xffffffffu, sum0, 1);
        sum0 += __shfl_xor_sync(0xffffffffu, sum0, 2);
        sum1 += __shfl_xor_sync(0xffffffffu, sum1, 1);
        sum1 += __shfl_xor_sync(0xffffffffu, sum1, 2);

        const float al0 = __expf(m0 - nm0), al1 = __expf(m1 - nm1);
        l0 = l0 * al0 + sum0; l1 = l1 * al1 + sum1;
        m0 = nm0; m1 = nm1;
#pragma unroll
        for (int j = 0; j < 8; j++) {
            oacc[j][0] *= al0; oacc[j][1] *= al0;
            oacc[j][2] *= al1; oacc[j][3] *= al1;
        }

        // O += P V  (P acc-layout -> A-fragment via quad shuffles;
        //            B fragment read directly from natural Vs[s][d])
        const int srcA = (lane & ~3) | (lc >> 1);
        const int srcB = srcA + 2;
#pragma unroll
        for (int jk = 0; jk < 8; jk++) {
            const uint32_t p0 = __float_as_uint(tf32r(sacc[jk][0]));
            const uint32_t p1 = __float_as_uint(tf32r(sacc[jk][1]));
            const uint32_t p2 = __float_as_uint(tf32r(sacc[jk][2]));
            const uint32_t p3 = __float_as_uint(tf32r(sacc[jk][3]));
            uint32_t a[4], x0, x1;
            x0 = __shfl_sync(0xffffffffu, p0, srcA);
            x1 = __shfl_sync(0xffffffffu, p1, srcA);
            a[0] = (lc & 1) ? x1 : x0;
            x0 = __shfl_sync(0xffffffffu, p2, srcA);
            x1 = __shfl_sync(0xffffffffu, p3, srcA);
            a[1] = (lc & 1) ? x1 : x0;
            x0 = __shfl_sync(0xffffffffu, p0, srcB);
            x1 = __shfl_sync(0xffffffffu, p1, srcB);
            a[2] = (lc & 1) ? x1 : x0;
            x0 = __shfl_sync(0xffffffffu, p2, srcB);
            x1 = __shfl_sync(0xffffffffu, p3, srcB);
            a[3] = (lc & 1) ? x1 : x0;

            const int kk = jk * 8;
#pragma unroll
            for (int j2 = 0; j2 < 8; j2++) {
                const int n = j2 * 8 + lr;
                uint32_t bf[2] = { __float_as_uint(Vs[(kk + lc) * FVL + n]),
                                   __float_as_uint(Vs[(kk + lc + 4) * FVL + n]) };
                mma_tf32(oacc[j2], a, bf);
            }
        }
        // no trailing barrier: next iteration's top barrier provides it
    }

    // Epilogue: normalize, rna (feeds out-proj as tf32), write [b][s][h*64+d]
    const float inv0 = 1.f / l0, inv1 = 1.f / l1;
    const int r0 = qt * 128 + wid * 16 + lr;
#pragma unroll
    for (int j2 = 0; j2 < 8; j2++) {
        const int col = h * 64 + j2 * 8 + 2 * lc;
        *(float2*)&g_attn[((size_t)b * Sn + r0) * Dn + col] =
            make_float2(tf32r(oacc[j2][0] * inv0), tf32r(oacc[j2][1] * inv0));
        *(float2*)&g_attn[((size_t)b * Sn + r0 + 8) * Dn + col] =
            make_float2(tf32r(oacc[j2][2] * inv1), tf32r(oacc[j2][3] * inv1));
    }
}

// ---------------------------------------------------------------------------

extern "C" void kernel_launch(void* const* d_in, const int* in_sizes, int n_in,
                              void* d_out, int out_size)
{
    const float* x     = (const float*)d_in[0];  // [B,S,D]
    const float* w_qkv = (const float*)d_in[1];  // [3,H,DK,D]
    const float* w_o   = (const float*)d_in[2];  // [D,D]
    float* out = (float*)d_out;                  // [B,S,D]

    const int M = Bn * Sn;   // 8192

    (void)cudaFuncSetAttribute(flash_tf32,
                               cudaFuncAttributeMaxDynamicSharedMemorySize, F_SMEM);
    (void)cudaFuncSetAttribute(gemm_tf32<0>,
                               cudaFuncAttributeMaxDynamicSharedMemorySize, G_SMEM);
    (void)cudaFuncSetAttribute(gemm_tf32<1>,
                               cudaFuncAttributeMaxDynamicSharedMemorySize, G_SMEM);

    float *xt, *wt, *wot, *attn;
    (void)cudaGetSymbolAddress((void**)&xt, g_xt);
    (void)cudaGetSymbolAddress((void**)&wt, g_wt);
    (void)cudaGetSymbolAddress((void**)&wot, g_wot);
    (void)cudaGetSymbolAddress((void**)&attn, g_attn);

    // 0) rna(tf32) pre-pass on inputs
    {
        int n4 = M * Dn / 4;
        cvt_kernel<<<(n4 + 255) / 256, 256>>>((const float4*)x, (float4*)xt, n4);
        n4 = 3 * Hn * DKn * Dn / 4;
        cvt_kernel<<<(n4 + 255) / 256, 256>>>((const float4*)w_qkv, (float4*)wt, n4);
        n4 = Dn * Dn / 4;
        cvt_kernel<<<(n4 + 255) / 256, 256>>>((const float4*)w_o, (float4*)wot, n4);
    }

    // 1) QKV projection (tf32 mma) -> g_qkv
    {
        dim3 grid(3 * Hn * DKn / 128, M / 128);  // (24, 64)
        gemm_tf32<0><<<grid, 128, G_SMEM>>>(xt, wt, nullptr, M, 3 * Hn * DKn, Dn);
    }

    // 2) Causal flash attention (tf32 mma) -> g_attn
    {
        dim3 grid(Sn / 128, Hn, Bn);  // (16, 16, 4)
        flash_tf32<<<grid, 256, F_SMEM>>>();
    }

    // 3) Output projection (tf32 mma) -> out
    {
        dim3 grid(Dn / 128, M / 128);  // (8, 64)
        gemm_tf32<1><<<grid, 128, G_SMEM>>>(attn, wot, out, M, Dn, Dn);
    }
}